// round 13
// baseline (speedup 1.0000x reference)
#include <cuda_runtime.h>
#include <cstdint>

#define K_DIM      128
#define O_DIM      128
#define CHUNK      16          // rows per quad ring slot
#define THREADS    384         // 12 warps = 3 quads x 4 warps (one per SMSP)
#define QTHREADS   128
#define LDS_STRIDE 136         // conflict-free LDS.64 phases: banks 8q+2t distinct
#define NBUF       6           // ring depth per quad (5 chunks in flight)
#define BUF_FLOATS (CHUNK * LDS_STRIDE)            // 2176
#define QUAD_FLOATS (NBUF * BUF_FLOATS)            // 13056
#define SMEM_BYTES (3 * QUAD_FLOATS * 4)           // 156672 B

// x feeds the tf32 MMA as raw fp32 bits (HW truncates to tf32).
// Mean relative shrink of truncation = 2^-11 * ln2 = 3.38e-4; compensate on W.
#define W_SCALE 1.000338f

__device__ __forceinline__ uint32_t cvt_tf32(float f) {
    uint32_t r;
    asm("cvt.rna.tf32.f32 %0, %1;" : "=r"(r) : "f"(f));
    return r;
}
__device__ __forceinline__ void cp_async16(uint32_t smem_addr, const void* gptr) {
    asm volatile("cp.async.cg.shared.global [%0], [%1], 16;" :: "r"(smem_addr), "l"(gptr));
}
__device__ __forceinline__ void cp_commit() {
    asm volatile("cp.async.commit_group;");
}
__device__ __forceinline__ void quad_bar(int id) {
    asm volatile("bar.sync %0, %1;" :: "r"(id), "r"(QTHREADS) : "memory");
}

// k-permutation: MMA step s, thread t covers logical k {t, t+4}, mapped to
// physical columns {8s+2t, 8s+2t+1}. Applied to BOTH A (x, smem col) and
// B (W, gmem col) -> GEMM unchanged; A frag = one LDS.64.

__global__ void __launch_bounds__(THREADS, 1)
qlinear_tf32_3q(const float* __restrict__ x,
                const float* __restrict__ W,
                float* __restrict__ out,
                int nrows, int nchunks)
{
    extern __shared__ float smem[];
    const int tid  = threadIdx.x;
    const int lane = tid & 31;
    const int wid  = tid >> 5;
    const int qid  = wid >> 2;          // quad 0..2 (= m-group)
    const int wo   = wid & 3;           // o-group within quad (= SMSP)
    const int tidq = tid & (QTHREADS - 1);

    float* qsm = smem + qid * QUAD_FLOATS;
    const uint32_t qsm_a = (uint32_t)__cvta_generic_to_shared(qsm);
    const int barid = 1 + qid;          // named barriers 1..3 (0 left for default)

    // this quad's chunk stream: interleaved 16-row chunks
    const int c0 = blockIdx.x * 3 + qid;
    const int st = gridDim.x * 3;

    auto stage = [&](int chunk, int buf) {
        if (chunk < nchunks) {
            int row0 = chunk * CHUNK;
            uint32_t base = qsm_a + (uint32_t)(buf * BUF_FLOATS) * 4;
            #pragma unroll
            for (int j = 0; j < 4; j++) {
                int flat = tidq + j * QTHREADS;     // 0..511 float4s
                int r  = flat >> 5;                 // 0..15
                int c4 = flat & 31;
                int gr = row0 + r;
                if (gr >= nrows) gr = nrows - 1;    // clamp: never OOB, data unused
                cp_async16(base + (uint32_t)(r * LDS_STRIDE + c4 * 4) * 4,
                           x + (size_t)gr * K_DIM + c4 * 4);
            }
        }
    };

    // start the ring: 5 chunks in flight (per-thread group counts all equal)
    stage(c0 + 0 * st, 0); cp_commit();
    stage(c0 + 1 * st, 1); cp_commit();
    stage(c0 + 2 * st, 2); cp_commit();
    stage(c0 + 3 * st, 3); cp_commit();
    stage(c0 + 4 * st, 4); cp_commit();

    // ---- per-warp geometry ----
    const int q = lane >> 2;        // groupID (0..7)
    const int t = lane & 3;         // threadID in group (0..3)

    // ---- B fragments straight from gmem (L2-served, one-time), permuted k ----
    uint32_t Bf[16][4][2];
    #pragma unroll
    for (int s = 0; s < 16; s++) {
        const int col = 8 * s + 2 * t;
        #pragma unroll
        for (int tt = 0; tt < 4; tt++) {
            const int n = wo * 32 + tt * 8 + q;
            float2 w = *reinterpret_cast<const float2*>(W + n * K_DIM + col);
            Bf[s][tt][0] = cvt_tf32(w.x * W_SCALE);
            Bf[s][tt][1] = cvt_tf32(w.y * W_SCALE);
        }
    }

    // ---- main pipeline (quad-local; quads never sync with each other) ----
    int idx = 0;
    for (int c = c0; c < nchunks; c += st, idx++) {
        const int buf = idx % NBUF;
        asm volatile("cp.async.wait_group 4;");     // own share of chunk c arrived
        quad_bar(barid);                            // all 4 warps' shares arrived;
                                                    // prev buffer drained by all

        // restage the slot consumed LAST iteration: safe post-barrier
        stage(c + 5 * st, (buf + 5) % NBUF);
        cp_commit();

        // thread's A base: row q, physical col 2t
        const float* xb = qsm + buf * BUF_FLOATS + q * LDS_STRIDE + 2 * t;

        float acc[4][4];
        #pragma unroll
        for (int tt = 0; tt < 4; tt++)
            #pragma unroll
            for (int e = 0; e < 4; e++) acc[tt][e] = 0.0f;

        #pragma unroll
        for (int s = 0; s < 16; s++) {
            const float* p = xb + s * 8;
            float2 f0 = *reinterpret_cast<const float2*>(p);                   // row q
            float2 f1 = *reinterpret_cast<const float2*>(p + 8 * LDS_STRIDE);  // row q+8
            const uint32_t a0 = __float_as_uint(f0.x);
            const uint32_t a2 = __float_as_uint(f0.y);
            const uint32_t a1 = __float_as_uint(f1.x);
            const uint32_t a3 = __float_as_uint(f1.y);
            #pragma unroll
            for (int tt = 0; tt < 4; tt++) {
                asm volatile(
                    "mma.sync.aligned.m16n8k8.row.col.f32.tf32.tf32.f32 "
                    "{%0,%1,%2,%3}, {%4,%5,%6,%7}, {%8,%9}, {%0,%1,%2,%3};"
                    : "+f"(acc[tt][0]), "+f"(acc[tt][1]),
                      "+f"(acc[tt][2]), "+f"(acc[tt][3])
                    : "r"(a0), "r"(a1), "r"(a2), "r"(a3),
                      "r"(Bf[s][tt][0]), "r"(Bf[s][tt][1]));
            }
        }

        // ---- epilogue: 8B sector-aligned float2 stores ----
        const int r1 = c * CHUNK + q;
        const int r2 = r1 + 8;
        #pragma unroll
        for (int tt = 0; tt < 4; tt++) {
            const int col = wo * 32 + tt * 8 + 2 * t;
            if (r1 < nrows)
                *reinterpret_cast<float2*>(out + (size_t)r1 * O_DIM + col) =
                    make_float2(acc[tt][0], acc[tt][1]);
            if (r2 < nrows)
                *reinterpret_cast<float2*>(out + (size_t)r2 * O_DIM + col) =
                    make_float2(acc[tt][2], acc[tt][3]);
        }
    }
}

extern "C" void kernel_launch(void* const* d_in, const int* in_sizes, int n_in,
                              void* d_out, int out_size)
{
    const float* x = (const float*)d_in[0];
    const float* W = (const float*)d_in[1];
    float* out = (float*)d_out;

    const int nrows   = in_sizes[0] / K_DIM;
    const int nchunks = (nrows + CHUNK - 1) / CHUNK;   // 16-row chunks

    cudaFuncSetAttribute(qlinear_tf32_3q,
                         cudaFuncAttributeMaxDynamicSharedMemorySize, SMEM_BYTES);

    int sms = 148;
    cudaDeviceGetAttribute(&sms, cudaDevAttrMultiProcessorCount, 0);
    int grid = sms;
    int need = (nchunks + 2) / 3;      // each CTA serves 3 chunk streams
    if (grid > need) grid = need;
    if (grid < 1) grid = 1;

    qlinear_tf32_3q<<<grid, THREADS, SMEM_BYTES>>>(x, W, out, nrows, nchunks);
}

// round 14
// speedup vs baseline: 1.0540x; 1.0540x over previous
#include <cuda_runtime.h>
#include <cuda.h>
#include <cstdint>

#define K_DIM      128
#define O_DIM      128
#define CHUNK      16          // rows per quad ring slot
#define THREADS    384         // 12 warps = 3 quads x 4 warps (one per SMSP)
#define QTHREADS   128
#define LDS_STRIDE 136         // conflict-free LDS.64 phases
#define NBUF       6           // x-ring depth per quad (5 chunks in flight)
#define BUF_FLOATS (CHUNK * LDS_STRIDE)            // 2176
#define QUAD_FLOATS (NBUF * BUF_FLOATS)            // 13056
// C-buffers first (1024-aligned slabs for SW128): per quad 2 parities x 4 slabs x 2KB
#define CSLAB      2048                            // 16 rows x 128 B
#define CBUF_QUAD  (2 * 4 * CSLAB)                 // 16384
#define CBUF_TOTAL (3 * CBUF_QUAD)                 // 49152
#define RING_OFF_F (CBUF_TOTAL / 4)                // float offset of x-ring
#define SMEM_BYTES (CBUF_TOTAL + 3 * QUAD_FLOATS * 4)   // 205824

// x feeds the tf32 MMA as raw fp32 bits (HW truncates to tf32).
// Mean relative shrink of truncation = 2^-11 * ln2 = 3.38e-4; compensate on W.
#define W_SCALE 1.000338f

__device__ __forceinline__ uint32_t cvt_tf32(float f) {
    uint32_t r;
    asm("cvt.rna.tf32.f32 %0, %1;" : "=r"(r) : "f"(f));
    return r;
}
__device__ __forceinline__ void cp_async16(uint32_t smem_addr, const void* gptr) {
    asm volatile("cp.async.cg.shared.global [%0], [%1], 16;" :: "r"(smem_addr), "l"(gptr));
}
__device__ __forceinline__ void cp_commit() {
    asm volatile("cp.async.commit_group;");
}
__device__ __forceinline__ void quad_bar(int id) {
    asm volatile("bar.sync %0, %1;" :: "r"(id), "r"(QTHREADS) : "memory");
}
__device__ __forceinline__ void sts32(uint32_t addr, float v) {
    asm volatile("st.shared.b32 [%0], %1;" :: "r"(addr), "f"(v) : "memory");
}
__device__ __forceinline__ void tma_store_2d(const CUtensorMap* map, int cx, int cy,
                                             uint32_t saddr) {
    asm volatile("cp.async.bulk.tensor.2d.global.shared::cta.tile.bulk_group "
                 "[%0, {%1, %2}], [%3];"
                 :: "l"(map), "r"(cx), "r"(cy), "r"(saddr) : "memory");
}

// k-permutation: MMA step s, thread t covers logical k {t, t+4} <- physical cols
// {8s+2t, 8s+2t+1}. Applied to both A (x, smem) and B (W, gmem): GEMM unchanged.
// n-permutation: n8-tile tt's logical col n <- physical col P(tt,n)=8tt+n/2+4(n&1)
// (choosing which W rows form the tile), making the C-slab STS.32s conflict-free.

__global__ void __launch_bounds__(THREADS, 1)
qlinear_tf32_tma(const __grid_constant__ CUtensorMap omap,
                 const float* __restrict__ x,
                 const float* __restrict__ W,
                 int nrows, int nchunks)
{
    extern __shared__ __align__(1024) float smem[];
    const int tid  = threadIdx.x;
    const int lane = tid & 31;
    const int wid  = tid >> 5;
    const int qid  = wid >> 2;          // quad 0..2
    const int wo   = wid & 3;           // o-group within quad (col group = slab)
    const int tidq = tid & (QTHREADS - 1);
    const uint32_t smem_a = (uint32_t)__cvta_generic_to_shared(smem);

    float* qsm = smem + RING_OFF_F + qid * QUAD_FLOATS;
    const uint32_t qsm_a  = smem_a + (uint32_t)(RING_OFF_F + qid * QUAD_FLOATS) * 4;
    const uint32_t cbuf_a = smem_a + (uint32_t)(qid * CBUF_QUAD);
    const int barid = 1 + qid;

    const int c0 = blockIdx.x * 3 + qid;        // this quad's interleaved chunk stream
    const int st = gridDim.x * 3;

    auto stage = [&](int chunk, int buf) {
        if (chunk < nchunks) {
            int row0 = chunk * CHUNK;
            uint32_t base = qsm_a + (uint32_t)(buf * BUF_FLOATS) * 4;
            #pragma unroll
            for (int j = 0; j < 4; j++) {
                int flat = tidq + j * QTHREADS;     // 0..511 float4s
                int r  = flat >> 5;
                int c4 = flat & 31;
                int gr = row0 + r;
                if (gr >= nrows) gr = nrows - 1;    // clamp: never OOB, data unused
                cp_async16(base + (uint32_t)(r * LDS_STRIDE + c4 * 4) * 4,
                           x + (size_t)gr * K_DIM + c4 * 4);
            }
        }
    };

    stage(c0 + 0 * st, 0); cp_commit();
    stage(c0 + 1 * st, 1); cp_commit();
    stage(c0 + 2 * st, 2); cp_commit();
    stage(c0 + 3 * st, 3); cp_commit();
    stage(c0 + 4 * st, 4); cp_commit();

    const int q = lane >> 2;        // groupID (0..7)
    const int t = lane & 3;         // threadID in group (0..3)

    // ---- B fragments from gmem (L2-served, one-time), k- and n-permuted ----
    uint32_t Bf[16][4][2];
    #pragma unroll
    for (int s = 0; s < 16; s++) {
        const int col = 8 * s + 2 * t;
        #pragma unroll
        for (int tt = 0; tt < 4; tt++) {
            // logical n = q of tile tt -> physical col P(tt,q)
            const int n = wo * 32 + 8 * tt + (q >> 1) + 4 * (q & 1);
            float2 w = *reinterpret_cast<const float2*>(W + n * K_DIM + col);
            Bf[s][tt][0] = cvt_tf32(w.x * W_SCALE);
            Bf[s][tt][1] = cvt_tf32(w.y * W_SCALE);
        }
    }

    // C-slab STS addressing: off = row*128 + tt*32 + j*16 + t*4, SW128 swizzle
    // = off ^ ((row&7)<<4); rows q and q+8 share (q&7) -> one static mask.
    const uint32_t sw_mask = (uint32_t)(q << 4);
    const uint32_t cA = (uint32_t)(q * 128 + t * 4);

    int idx = 0;
    for (int c = c0; c < nchunks; c += st, idx++) {
        const int buf = idx % NBUF;
        asm volatile("cp.async.wait_group 4;");
        quad_bar(barid);                            // chunk c staged for whole quad

        stage(c + 5 * st, (buf + 5) % NBUF);        // refill slot consumed last iter
        cp_commit();

        const float* xb = qsm + buf * BUF_FLOATS + q * LDS_STRIDE + 2 * t;

        float acc[4][4];
        #pragma unroll
        for (int tt = 0; tt < 4; tt++)
            #pragma unroll
            for (int e = 0; e < 4; e++) acc[tt][e] = 0.0f;

        #pragma unroll
        for (int s = 0; s < 16; s++) {
            const float* p = xb + s * 8;
            float2 f0 = *reinterpret_cast<const float2*>(p);                   // row q
            float2 f1 = *reinterpret_cast<const float2*>(p + 8 * LDS_STRIDE);  // row q+8
            const uint32_t a0 = __float_as_uint(f0.x);
            const uint32_t a2 = __float_as_uint(f0.y);
            const uint32_t a1 = __float_as_uint(f1.x);
            const uint32_t a3 = __float_as_uint(f1.y);
            #pragma unroll
            for (int tt = 0; tt < 4; tt++) {
                asm volatile(
                    "mma.sync.aligned.m16n8k8.row.col.f32.tf32.tf32.f32 "
                    "{%0,%1,%2,%3}, {%4,%5,%6,%7}, {%8,%9}, {%0,%1,%2,%3};"
                    : "+f"(acc[tt][0]), "+f"(acc[tt][1]),
                      "+f"(acc[tt][2]), "+f"(acc[tt][3])
                    : "r"(a0), "r"(a1), "r"(a2), "r"(a3),
                      "r"(Bf[s][tt][0]), "r"(Bf[s][tt][1]));
            }
        }

        // ---- epilogue: conflict-free STS.32 into SW128 C-slab, then TMA store ----
        const int par = idx & 1;
        const uint32_t slab = cbuf_a + (uint32_t)(par * 4 + wo) * CSLAB;
        const uint32_t b0 = slab + cA;
        #pragma unroll
        for (int tt = 0; tt < 4; tt++) {
            const uint32_t clo = ((uint32_t)(tt * 32)      ^ sw_mask);
            const uint32_t chi = ((uint32_t)(tt * 32 + 16) ^ sw_mask);
            sts32(b0 + clo,        acc[tt][0]);     // row q,   col 8tt+t
            sts32(b0 + chi,        acc[tt][1]);     // row q,   col 8tt+t+4
            sts32(b0 + clo + 1024, acc[tt][2]);     // row q+8
            sts32(b0 + chi + 1024, acc[tt][3]);
        }
        quad_bar(barid);                            // all 4 slabs written

        if (tidq == 0) {
            asm volatile("fence.proxy.async.shared::cta;" ::: "memory");
            const int row0 = c * CHUNK;
            #pragma unroll
            for (int g = 0; g < 4; g++)
                tma_store_2d(&omap, 32 * g, row0,
                             cbuf_a + (uint32_t)(par * 4 + g) * CSLAB);
            asm volatile("cp.async.bulk.commit_group;" ::: "memory");
            // keep <=1 bulk group unread: parity buffer from 2 chunks ago is free
            asm volatile("cp.async.bulk.wait_group.read 1;" ::: "memory");
        }
        // next reuse of this parity is 2 chunks away, behind two top-of-loop bars
    }

    // drain outstanding bulk stores before exit
    if (tidq == 0)
        asm volatile("cp.async.bulk.wait_group 0;" ::: "memory");
}

extern "C" void kernel_launch(void* const* d_in, const int* in_sizes, int n_in,
                              void* d_out, int out_size)
{
    const float* x = (const float*)d_in[0];
    const float* W = (const float*)d_in[1];
    float* out = (float*)d_out;

    const int nrows   = in_sizes[0] / K_DIM;
    const int nchunks = (nrows + CHUNK - 1) / CHUNK;

    // TMA descriptor for out: [128 f32 cols, nrows], box [32,16], SW128
    typedef CUresult (*EncFn)(CUtensorMap*, CUtensorMapDataType, cuuint32_t, void*,
                              const cuuint64_t*, const cuuint64_t*, const cuuint32_t*,
                              const cuuint32_t*, CUtensorMapInterleave, CUtensorMapSwizzle,
                              CUtensorMapL2promotion, CUtensorMapFloatOOBfill);
    void* fp = nullptr;
    cudaDriverEntryPointQueryResult qr;
    cudaGetDriverEntryPointByVersion("cuTensorMapEncodeTiled", &fp, 12000,
                                     cudaEnableDefault, &qr);
    EncFn enc = (EncFn)fp;

    CUtensorMap omap;
    cuuint64_t dims[2]    = {O_DIM, (cuuint64_t)nrows};
    cuuint64_t strides[1] = {O_DIM * sizeof(float)};
    cuuint32_t box[2]     = {32, CHUNK};           // 32 f32 = 128 B (SW128 atom)
    cuuint32_t es[2]      = {1, 1};
    enc(&omap, CU_TENSOR_MAP_DATA_TYPE_FLOAT32, 2, (void*)out, dims, strides, box, es,
        CU_TENSOR_MAP_INTERLEAVE_NONE, CU_TENSOR_MAP_SWIZZLE_128B,
        CU_TENSOR_MAP_L2_PROMOTION_L2_128B, CU_TENSOR_MAP_FLOAT_OOB_FILL_NONE);

    cudaFuncSetAttribute(qlinear_tf32_tma,
                         cudaFuncAttributeMaxDynamicSharedMemorySize, SMEM_BYTES);

    int sms = 148;
    cudaDeviceGetAttribute(&sms, cudaDevAttrMultiProcessorCount, 0);
    int grid = sms;
    int need = (nchunks + 2) / 3;
    if (grid > need) grid = need;
    if (grid < 1) grid = 1;

    qlinear_tf32_tma<<<grid, THREADS, SMEM_BYTES>>>(omap, x, W, nrows, nchunks);
}

// round 15
// speedup vs baseline: 1.1475x; 1.0887x over previous
#include <cuda_runtime.h>
#include <cuda.h>
#include <cstdint>

#define K_DIM      128
#define O_DIM      128
#define CHUNK      16          // rows per quad ring slot
#define THREADS    384         // 12 warps = 3 quads x 4 warps (one per SMSP)
#define QTHREADS   128
#define LDS_STRIDE 136         // conflict-free LDS.64 phases
#define NBUF       6           // x-ring depth per quad (5 chunks in flight)
#define BUF_FLOATS (CHUNK * LDS_STRIDE)            // 2176
#define QUAD_FLOATS (NBUF * BUF_FLOATS)            // 13056
// C-buffers first (1024-aligned slabs for SW128): per quad 2 parities x 4 slabs x 2KB
#define CSLAB      2048                            // 16 rows x 128 B
#define CBUF_QUAD  (2 * 4 * CSLAB)                 // 16384
#define CBUF_TOTAL (3 * CBUF_QUAD)                 // 49152
#define RING_OFF_F (CBUF_TOTAL / 4)
#define SMEM_BYTES (CBUF_TOTAL + 3 * QUAD_FLOATS * 4)   // 205824

// x feeds the tf32 MMA as raw fp32 bits (HW truncates to tf32).
// Mean relative shrink of truncation = 2^-11 * ln2 = 3.38e-4; compensate on W.
#define W_SCALE 1.000338f

__device__ __forceinline__ uint32_t cvt_tf32(float f) {
    uint32_t r;
    asm("cvt.rna.tf32.f32 %0, %1;" : "=r"(r) : "f"(f));
    return r;
}
__device__ __forceinline__ void cp_async16(uint32_t smem_addr, const void* gptr) {
    asm volatile("cp.async.cg.shared.global [%0], [%1], 16;" :: "r"(smem_addr), "l"(gptr));
}
__device__ __forceinline__ void cp_commit() {
    asm volatile("cp.async.commit_group;");
}
__device__ __forceinline__ void quad_bar(int id) {
    asm volatile("bar.sync %0, %1;" :: "r"(id), "r"(QTHREADS) : "memory");
}
__device__ __forceinline__ void sts32(uint32_t addr, float v) {
    asm volatile("st.shared.b32 [%0], %1;" :: "r"(addr), "f"(v) : "memory");
}
__device__ __forceinline__ void tma_store_2d(const CUtensorMap* map, int cx, int cy,
                                             uint32_t saddr) {
    asm volatile("cp.async.bulk.tensor.2d.global.shared::cta.tile.bulk_group "
                 "[%0, {%1, %2}], [%3];"
                 :: "l"(map), "r"(cx), "r"(cy), "r"(saddr) : "memory");
}

// k-permutation: MMA step s, thread t covers logical k {t, t+4} <- physical cols
// {8s+2t, 8s+2t+1}; applied to both A and B -> GEMM unchanged.
// n-permutation: n8-tile tt logical col n <- physical col 8tt + n/2 + 4(n&1)
// -> conflict-free C-slab STS.32.

__global__ void __launch_bounds__(THREADS, 1)
qlinear_tf32_tma2(const __grid_constant__ CUtensorMap omap,
                  const float* __restrict__ x,
                  const float* __restrict__ W,
                  int nrows, int nchunks)
{
    extern __shared__ __align__(1024) float smem[];
    const int tid  = threadIdx.x;
    const int lane = tid & 31;
    const int wid  = tid >> 5;
    const int qid  = wid >> 2;          // quad 0..2
    const int wo   = wid & 3;           // o-group within quad (col group = slab)
    const int tidq = tid & (QTHREADS - 1);
    const uint32_t smem_a = (uint32_t)__cvta_generic_to_shared(smem);

    float* qsm = smem + RING_OFF_F + qid * QUAD_FLOATS;
    const uint32_t qsm_a  = smem_a + (uint32_t)(RING_OFF_F + qid * QUAD_FLOATS) * 4;
    const uint32_t cbuf_a = smem_a + (uint32_t)(qid * CBUF_QUAD);
    const int barid = 1 + qid;

    const int c0 = blockIdx.x * 3 + qid;        // this quad's interleaved chunk stream
    const int st = gridDim.x * 3;

    auto stage = [&](int chunk, int buf) {
        if (chunk < nchunks) {
            int row0 = chunk * CHUNK;
            uint32_t base = qsm_a + (uint32_t)(buf * BUF_FLOATS) * 4;
            #pragma unroll
            for (int j = 0; j < 4; j++) {
                int flat = tidq + j * QTHREADS;     // 0..511 float4s
                int r  = flat >> 5;
                int c4 = flat & 31;
                int gr = row0 + r;
                if (gr >= nrows) gr = nrows - 1;    // clamp: never OOB, data unused
                cp_async16(base + (uint32_t)(r * LDS_STRIDE + c4 * 4) * 4,
                           x + (size_t)gr * K_DIM + c4 * 4);
            }
        }
    };

    stage(c0 + 0 * st, 0); cp_commit();
    stage(c0 + 1 * st, 1); cp_commit();
    stage(c0 + 2 * st, 2); cp_commit();
    stage(c0 + 3 * st, 3); cp_commit();
    stage(c0 + 4 * st, 4); cp_commit();

    const int q = lane >> 2;        // groupID (0..7)
    const int t = lane & 3;         // threadID in group (0..3)

    // ---- B fragments from gmem (L2-served, one-time), k- and n-permuted ----
    uint32_t Bf[16][4][2];
    #pragma unroll
    for (int s = 0; s < 16; s++) {
        const int col = 8 * s + 2 * t;
        #pragma unroll
        for (int tt = 0; tt < 4; tt++) {
            const int n = wo * 32 + 8 * tt + (q >> 1) + 4 * (q & 1);
            float2 w = *reinterpret_cast<const float2*>(W + n * K_DIM + col);
            Bf[s][tt][0] = cvt_tf32(w.x * W_SCALE);
            Bf[s][tt][1] = cvt_tf32(w.y * W_SCALE);
        }
    }

    // C-slab STS addressing: off = row*128 + tt*32 + j*16 + t*4, SW128 swizzle
    const uint32_t sw_mask = (uint32_t)(q << 4);
    const uint32_t cA = (uint32_t)(q * 128 + t * 4);
    const uint32_t thread_xoff = (uint32_t)(q * LDS_STRIDE + 2 * t);

    // ---- main pipeline: ring fully unrolled so buf/parity are compile-time ----
    int c = c0;
    while (c < nchunks) {
        #pragma unroll
        for (int u = 0; u < NBUF; u++) {
            if (c >= nchunks) break;

            asm volatile("cp.async.wait_group 4;");
            quad_bar(barid);                        // chunk staged for whole quad;
                                                    // also orders parity-slab reuse

            stage(c + 5 * st, (u + 5) % NBUF);      // compile-time slot
            cp_commit();

            const float* xb = qsm + u * BUF_FLOATS + thread_xoff;

            float acc[4][4];
            #pragma unroll
            for (int tt = 0; tt < 4; tt++)
                #pragma unroll
                for (int e = 0; e < 4; e++) acc[tt][e] = 0.0f;

            #pragma unroll
            for (int s = 0; s < 16; s++) {
                const float* p = xb + s * 8;
                float2 f0 = *reinterpret_cast<const float2*>(p);
                float2 f1 = *reinterpret_cast<const float2*>(p + 8 * LDS_STRIDE);
                const uint32_t a0 = __float_as_uint(f0.x);
                const uint32_t a2 = __float_as_uint(f0.y);
                const uint32_t a1 = __float_as_uint(f1.x);
                const uint32_t a3 = __float_as_uint(f1.y);
                #pragma unroll
                for (int tt = 0; tt < 4; tt++) {
                    asm volatile(
                        "mma.sync.aligned.m16n8k8.row.col.f32.tf32.tf32.f32 "
                        "{%0,%1,%2,%3}, {%4,%5,%6,%7}, {%8,%9}, {%0,%1,%2,%3};"
                        : "+f"(acc[tt][0]), "+f"(acc[tt][1]),
                          "+f"(acc[tt][2]), "+f"(acc[tt][3])
                        : "r"(a0), "r"(a1), "r"(a2), "r"(a3),
                          "r"(Bf[s][tt][0]), "r"(Bf[s][tt][1]));
                }
            }

            // ---- warp-local epilogue: STS -> fence -> syncwarp -> lane0 TMA ----
            const uint32_t slab = cbuf_a + (uint32_t)(((u & 1) * 4 + wo) * CSLAB);
            const uint32_t b0 = slab + cA;
            #pragma unroll
            for (int tt = 0; tt < 4; tt++) {
                const uint32_t clo = ((uint32_t)(tt * 32)      ^ sw_mask);
                const uint32_t chi = ((uint32_t)(tt * 32 + 16) ^ sw_mask);
                sts32(b0 + clo,        acc[tt][0]);
                sts32(b0 + chi,        acc[tt][1]);
                sts32(b0 + clo + 1024, acc[tt][2]);
                sts32(b0 + chi + 1024, acc[tt][3]);
            }
            asm volatile("fence.proxy.async.shared::cta;" ::: "memory");
            __syncwarp();
            if (lane == 0) {
                tma_store_2d(&omap, 32 * wo, c * CHUNK, slab);
                asm volatile("cp.async.bulk.commit_group;" ::: "memory");
                // keep <=1 unread group: this parity's slab from 2 chunks ago is free
                asm volatile("cp.async.bulk.wait_group.read 1;" ::: "memory");
            }

            c += st;
        }
    }

    // drain outstanding bulk stores before exit
    if (lane == 0)
        asm volatile("cp.async.bulk.wait_group 0;" ::: "memory");
}

extern "C" void kernel_launch(void* const* d_in, const int* in_sizes, int n_in,
                              void* d_out, int out_size)
{
    const float* x = (const float*)d_in[0];
    const float* W = (const float*)d_in[1];
    float* out = (float*)d_out;

    const int nrows   = in_sizes[0] / K_DIM;
    const int nchunks = (nrows + CHUNK - 1) / CHUNK;

    typedef CUresult (*EncFn)(CUtensorMap*, CUtensorMapDataType, cuuint32_t, void*,
                              const cuuint64_t*, const cuuint64_t*, const cuuint32_t*,
                              const cuuint32_t*, CUtensorMapInterleave, CUtensorMapSwizzle,
                              CUtensorMapL2promotion, CUtensorMapFloatOOBfill);
    void* fp = nullptr;
    cudaDriverEntryPointQueryResult qr;
    cudaGetDriverEntryPointByVersion("cuTensorMapEncodeTiled", &fp, 12000,
                                     cudaEnableDefault, &qr);
    EncFn enc = (EncFn)fp;

    CUtensorMap omap;
    cuuint64_t dims[2]    = {O_DIM, (cuuint64_t)nrows};
    cuuint64_t strides[1] = {O_DIM * sizeof(float)};
    cuuint32_t box[2]     = {32, CHUNK};           // 32 f32 = 128 B (SW128 atom)
    cuuint32_t es[2]      = {1, 1};
    enc(&omap, CU_TENSOR_MAP_DATA_TYPE_FLOAT32, 2, (void*)out, dims, strides, box, es,
        CU_TENSOR_MAP_INTERLEAVE_NONE, CU_TENSOR_MAP_SWIZZLE_128B,
        CU_TENSOR_MAP_L2_PROMOTION_L2_128B, CU_TENSOR_MAP_FLOAT_OOB_FILL_NONE);

    cudaFuncSetAttribute(qlinear_tf32_tma2,
                         cudaFuncAttributeMaxDynamicSharedMemorySize, SMEM_BYTES);

    int sms = 148;
    cudaDeviceGetAttribute(&sms, cudaDevAttrMultiProcessorCount, 0);
    int grid = sms;
    int need = (nchunks + 2) / 3;
    if (grid > need) grid = need;
    if (grid < 1) grid = 1;

    qlinear_tf32_tma2<<<grid, THREADS, SMEM_BYTES>>>(omap, x, W, nrows, nchunks);
}